// round 7
// baseline (speedup 1.0000x reference)
#include <cuda_runtime.h>
#include <cuda_bf16.h>
#include <math.h>

#define N_NODES   100000
#define N_EDGES   3200000
#define N_GRAPHS  512
#define FEAT      128
#define H1DIM     32
#define H2DIM     16
#define NCLS      10

#define SCAN_T    1024
#define PER_T     98      // ceil(100000/1024)

// ---------------- scratch (device globals; no allocation allowed) ----------
__device__ __align__(16) int   g_degi  [N_NODES];       // in-degree (edges only)
__device__ __align__(16) int   g_rowptr[N_NODES + 1];   // CSR row offsets
__device__ __align__(16) int   g_cursor[N_NODES];       // fill cursors
__device__ __align__(16) int   g_csrc  [N_EDGES];       // CSR src indices (dst-sorted)
__device__ __align__(16) float g_dinv  [N_NODES];
__device__ __align__(16) float g_h1    [N_NODES * H1DIM];
__device__ __align__(16) float g_agg1  [N_NODES * H1DIM];
__device__ __align__(16) float g_h2    [N_NODES * H2DIM];
__device__ __align__(16) float g_agg2  [N_NODES * H2DIM];
__device__ __align__(16) float g_sum   [N_GRAPHS * H2DIM];
__device__ __align__(16) float g_cnt   [N_GRAPHS];
__device__ int g_ei64;    // 1 if edge_index is int64, else int32
__device__ int g_bat64;   // 1 if batch_index is int64, else int32

__device__ __forceinline__ int clampi(int v, int lo, int hi) {
    return v < lo ? lo : (v > hi ? hi : v);
}

// TF32 rounding (matches XLA/cuBLAS default f32 matmul precision on GPU)
__device__ __forceinline__ float tf32r(float v) {
    unsigned r;
    asm("cvt.rna.tf32.f32 %0, %1;" : "=r"(r) : "f"(v));
    return __uint_as_float(r);
}

// dtype-agnostic index load: i-th logical element of an index array
__device__ __forceinline__ int load_idx(const void* p, long long i, int is64) {
    if (is64) return (int)((const long long*)p)[i];
    return ((const int*)p)[i];
}

// ---------------- 0. probe dtypes of integer inputs -----------------------
// All probed 32-bit word indices are IN-BOUNDS for BOTH dtype interpretations.
// edge head: words 2k+1, k<64 (max word 129 < 6.4M). int64 -> upper halves of
//   elements (values < 2^31) = 0. int32 -> src values ei[1],ei[3].. (nonzero whp).
// batch middle: words 2k+1, k in [40000,40064) (max word 80129 < 100000).
//   int64 -> upper halves of elements ~40000 = 0. int32 -> batch[80001..]
//   ~ graph id ~410 (sorted, > 0 with certainty) -> nonzero.
__global__ void k_probe(const int* __restrict__ ei32, const int* __restrict__ bat32) {
    if (threadIdx.x == 0) {
        int all0 = 1;
        for (int k = 0; k < 64; k++) if (ei32[2 * k + 1] != 0) { all0 = 0; break; }
        g_ei64 = all0;
        int all0b = 1;
        for (int k = 40000; k < 40064; k++)
            if (bat32[2 * k + 1] != 0) { all0b = 0; break; }
        g_bat64 = all0b;
    }
}

// ---------------- 1. init: zero degree + pool accumulators ----------------
__global__ void k_init(void) {
    int i = blockIdx.x * blockDim.x + threadIdx.x;
    if (i < N_NODES) g_degi[i] = 0;
    if (i < N_GRAPHS * H2DIM) g_sum[i] = 0.0f;
    if (i < N_GRAPHS) g_cnt[i] = 0.0f;
}

// ---------------- 2. in-degree over edge dst (int atomics) ----------------
__global__ void k_deg(const void* __restrict__ ei) {
    int e = blockIdx.x * blockDim.x + threadIdx.x;
    int is64 = g_ei64;
    if (e < N_EDGES) {
        int d = clampi(load_idx(ei, (long long)N_EDGES + e, is64), 0, N_NODES - 1);
        atomicAdd(&g_degi[d], 1);
    }
}

// ---------------- 3. single-block exclusive scan -> rowptr, cursor --------
__global__ void k_scan(void) {
    __shared__ int ssum[SCAN_T];
    int t = threadIdx.x;
    int begin = t * PER_T;
    int end   = begin + PER_T; if (end > N_NODES) end = N_NODES;
    int local = 0;
    for (int i = begin; i < end; i++) local += g_degi[i];
    ssum[t] = local;
    __syncthreads();
    for (int off = 1; off < SCAN_T; off <<= 1) {
        int v = (t >= off) ? ssum[t - off] : 0;
        __syncthreads();
        ssum[t] += v;
        __syncthreads();
    }
    int run = (t == 0) ? 0 : ssum[t - 1];   // exclusive base for this thread
    for (int i = begin; i < end; i++) {
        g_rowptr[i] = run;
        g_cursor[i] = run;
        run += g_degi[i];
    }
    if (t == SCAN_T - 1) g_rowptr[N_NODES] = ssum[SCAN_T - 1];
}

// ---------------- 4. dinv = rsqrt(in-degree + self loop) ------------------
__global__ void k_dinv(void) {
    int i = blockIdx.x * blockDim.x + threadIdx.x;
    if (i < N_NODES) g_dinv[i] = rsqrtf((float)(g_degi[i] + 1));
}

// ---------------- 5. CSR fill: scatter src into dst buckets ---------------
__global__ void k_fill(const void* __restrict__ ei) {
    int e = blockIdx.x * blockDim.x + threadIdx.x;
    int is64 = g_ei64;
    if (e < N_EDGES) {
        int s = clampi(load_idx(ei, e, is64), 0, N_NODES - 1);
        int d = clampi(load_idx(ei, (long long)N_EDGES + e, is64), 0, N_NODES - 1);
        int pos = atomicAdd(&g_cursor[d], 1);
        g_csrc[clampi(pos, 0, N_EDGES - 1)] = s;
    }
}

// ---------------- 6. GEMM1: h1 = X @ W1   (warp per row, tf32 inputs) -----
__global__ void k_gemm1(const float* __restrict__ x, const float* __restrict__ W1) {
    __shared__ float sW[FEAT * H1DIM];           // 16 KB
    for (int i = threadIdx.x; i < FEAT * H1DIM; i += blockDim.x) sW[i] = tf32r(W1[i]);
    __syncthreads();
    int warp = threadIdx.x >> 5, lane = threadIdx.x & 31;
    int row = blockIdx.x * 8 + warp;
    if (row >= N_NODES) return;
    float4 xv = reinterpret_cast<const float4*>(x)[row * (FEAT / 4) + lane];
    xv.x = tf32r(xv.x); xv.y = tf32r(xv.y); xv.z = tf32r(xv.z); xv.w = tf32r(xv.w);
    float acc = 0.0f;
#pragma unroll
    for (int r = 0; r < 32; r++) {
        float bx = __shfl_sync(0xffffffffu, xv.x, r);
        float by = __shfl_sync(0xffffffffu, xv.y, r);
        float bz = __shfl_sync(0xffffffffu, xv.z, r);
        float bw = __shfl_sync(0xffffffffu, xv.w, r);
        int k = r * 4;
        acc = fmaf(bx, sW[(k + 0) * H1DIM + lane], acc);
        acc = fmaf(by, sW[(k + 1) * H1DIM + lane], acc);
        acc = fmaf(bz, sW[(k + 2) * H1DIM + lane], acc);
        acc = fmaf(bw, sW[(k + 3) * H1DIM + lane], acc);
    }
    g_h1[row * H1DIM + lane] = acc;
}

// ---------------- 7. agg1: warp-per-node gather (no atomics) --------------
__global__ void k_agg1(void) {
    int warp = (blockIdx.x * blockDim.x + threadIdx.x) >> 5;
    int lane = threadIdx.x & 31;
    if (warp >= N_NODES) return;
    int d = warp;
    int start = g_rowptr[d], end = g_rowptr[d + 1];
    float dvd = g_dinv[d];
    // self loop: h1[d] * dvd ; whole acc multiplied by dvd at the end -> dvd^2
    float acc = g_h1[d * H1DIM + lane] * dvd;
    for (int base = start; base < end; base += 32) {
        int n = end - base;
        int s = 0; float dvs = 0.0f;
        if (lane < n) { s = g_csrc[base + lane]; dvs = g_dinv[s]; }
        int m = n < 32 ? n : 32;
        for (int j = 0; j < m; j++) {
            int   sj = __shfl_sync(0xffffffffu, s,   j);
            float dj = __shfl_sync(0xffffffffu, dvs, j);
            acc = fmaf(g_h1[sj * H1DIM + lane], dj, acc);
        }
    }
    g_agg1[d * H1DIM + lane] = acc * dvd;
}

// ---------------- 8. fused bias1+relu + GEMM2 (tf32 inputs) ---------------
__global__ void k_gemm2(const float* __restrict__ b1, const float* __restrict__ W2) {
    __shared__ float sW[H1DIM * H2DIM];          // 2 KB
    __shared__ float sb[H1DIM];
    for (int i = threadIdx.x; i < H1DIM * H2DIM; i += blockDim.x) sW[i] = tf32r(W2[i]);
    if (threadIdx.x < H1DIM) sb[threadIdx.x] = b1[threadIdx.x];
    __syncthreads();
    int warp = threadIdx.x >> 5, lane = threadIdx.x & 31;
    int row = blockIdx.x * 8 + warp;
    if (row >= N_NODES) return;
    float v = g_agg1[row * H1DIM + lane] + sb[lane];
    v = tf32r(fmaxf(v, 0.0f));
    int j = lane & 15;
    float acc = 0.0f;
#pragma unroll
    for (int r = 0; r < 32; r++) {
        float xb = __shfl_sync(0xffffffffu, v, r);
        acc = fmaf(xb, sW[r * H2DIM + j], acc);
    }
    if (lane < H2DIM) g_h2[row * H2DIM + lane] = acc;
}

// ---------------- 9. agg2: warp-per-node gather (H2 = 16) -----------------
__global__ void k_agg2(void) {
    int warp = (blockIdx.x * blockDim.x + threadIdx.x) >> 5;
    int lane = threadIdx.x & 31;
    if (warp >= N_NODES) return;
    int d = warp;
    int start = g_rowptr[d], end = g_rowptr[d + 1];
    float dvd = g_dinv[d];
    float acc = (lane < H2DIM) ? g_h2[d * H2DIM + lane] * dvd : 0.0f;
    for (int base = start; base < end; base += 32) {
        int n = end - base;
        int s = 0; float dvs = 0.0f;
        if (lane < n) { s = g_csrc[base + lane]; dvs = g_dinv[s]; }
        int m = n < 32 ? n : 32;
        for (int j = 0; j < m; j++) {
            int   sj = __shfl_sync(0xffffffffu, s,   j);
            float dj = __shfl_sync(0xffffffffu, dvs, j);
            if (lane < H2DIM)
                acc = fmaf(g_h2[sj * H2DIM + lane], dj, acc);
        }
    }
    if (lane < H2DIM) g_agg2[d * H2DIM + lane] = acc * dvd;
}

// ---------------- 10. pool: relu(agg2+b2) -> per-graph sums (scalar) ------
__global__ void k_pool(const float* __restrict__ b2, const void* __restrict__ batch) {
    int idx = blockIdx.x * blockDim.x + threadIdx.x;
    int node = idx >> 4, c = idx & 15;
    int is64 = g_bat64;
    if (node >= N_NODES) return;
    int g = clampi(load_idx(batch, node, is64), 0, N_GRAPHS - 1);
    float v = fmaxf(g_agg2[node * H2DIM + c] + b2[c], 0.0f);
    atomicAdd(&g_sum[g * H2DIM + c], v);
    if (c == 0) atomicAdd(&g_cnt[g], 1.0f);
}

// ---------------- 11. final: mean, FC (tf32), softmax ---------------------
__global__ void k_final(const float* __restrict__ fc_w, const float* __restrict__ fc_b,
                        float* __restrict__ out) {
    int g = blockIdx.x * blockDim.x + threadIdx.x;
    if (g >= N_GRAPHS) return;
    float inv = 1.0f / fmaxf(g_cnt[g], 1.0f);
    float p[H2DIM];
#pragma unroll
    for (int j = 0; j < H2DIM; j++) p[j] = tf32r(g_sum[g * H2DIM + j] * inv);
    float logit[NCLS];
#pragma unroll
    for (int c = 0; c < NCLS; c++) {
        float acc = 0.0f;
#pragma unroll
        for (int j = 0; j < H2DIM; j++) acc = fmaf(p[j], tf32r(fc_w[j * NCLS + c]), acc);
        logit[c] = acc + fc_b[c];
    }
    float m = logit[0];
#pragma unroll
    for (int c = 1; c < NCLS; c++) m = fmaxf(m, logit[c]);
    float s = 0.0f;
#pragma unroll
    for (int c = 0; c < NCLS; c++) { logit[c] = expf(logit[c] - m); s += logit[c]; }
    float invs = 1.0f / s;
#pragma unroll
    for (int c = 0; c < NCLS; c++) out[g * NCLS + c] = logit[c] * invs;
}

// ---------------------------------------------------------------------------
extern "C" void kernel_launch(void* const* d_in, const int* in_sizes, int n_in,
                              void* d_out, int out_size) {
    // PRIMARY: positional binding in reference-dict order
    const float *x   = (n_in > 0) ? (const float*)d_in[0] : 0;
    const void  *ei  = (n_in > 1) ? d_in[1]               : 0;
    const void  *bat = (n_in > 2) ? d_in[2]               : 0;
    const float *W1  = (n_in > 3) ? (const float*)d_in[3] : 0;
    const float *b1  = (n_in > 4) ? (const float*)d_in[4] : 0;
    const float *W2  = (n_in > 5) ? (const float*)d_in[5] : 0;
    const float *b2  = (n_in > 6) ? (const float*)d_in[6] : 0;
    const float *fcw = (n_in > 7) ? (const float*)d_in[7] : 0;
    const float *fcb = (n_in > 8) ? (const float*)d_in[8] : 0;

    // SECONDARY: override by exact element-count match (all counts distinct).
    for (int i = 0; i < n_in; i++) {
        switch (in_sizes[i]) {
            case N_NODES * FEAT:   x   = (const float*)d_in[i]; break;  // 12.8M
            case 2 * N_EDGES:      ei  = d_in[i];               break;  // 6.4M
            case N_NODES:          bat = d_in[i];               break;  // 100k
            case FEAT * H1DIM:     W1  = (const float*)d_in[i]; break;  // 4096
            case H1DIM:            b1  = (const float*)d_in[i]; break;  // 32
            case H1DIM * H2DIM:    W2  = (const float*)d_in[i]; break;  // 512
            case H2DIM:            b2  = (const float*)d_in[i]; break;  // 16
            case H2DIM * NCLS:     fcw = (const float*)d_in[i]; break;  // 160
            case NCLS:             fcb = (const float*)d_in[i]; break;  // 10
            default: break;
        }
    }
    float* out = (float*)d_out;
    if (!x || !ei || !bat || !W1 || !b1 || !W2 || !b2 || !fcw || !fcb || !out) return;

    const int T = 256;
    k_probe<<<1, 32>>>((const int*)ei, (const int*)bat);
    k_init <<<(N_NODES + T - 1) / T, T>>>();
    k_deg  <<<(N_EDGES + T - 1) / T, T>>>(ei);
    k_scan <<<1, SCAN_T>>>();
    k_dinv <<<(N_NODES + T - 1) / T, T>>>();
    k_fill <<<(N_EDGES + T - 1) / T, T>>>(ei);
    k_gemm1<<<(N_NODES + 7) / 8, T>>>(x, W1);
    k_agg1 <<<(N_NODES * 32 + T - 1) / T, T>>>();
    k_gemm2<<<(N_NODES + 7) / 8, T>>>(b1, W2);
    k_agg2 <<<(N_NODES * 32 + T - 1) / T, T>>>();
    k_pool <<<(N_NODES * H2DIM + T - 1) / T, T>>>(b2, bat);
    k_final<<<(N_GRAPHS + T - 1) / T, T>>>(fcw, fcb, out);
}

// round 8
// speedup vs baseline: 1.3899x; 1.3899x over previous
#include <cuda_runtime.h>
#include <cuda_bf16.h>
#include <math.h>

#define N_NODES   100000
#define N_EDGES   3200000
#define N_GRAPHS  512
#define FEAT      128
#define H1DIM     32
#define H2DIM     16
#define NCLS      10

#define SB        1024                         // scan block size
#define NBLK      ((N_NODES + SB - 1) / SB)    // 98

// ---------------- scratch (device globals; no allocation allowed) ----------
__device__ __align__(16) int   g_degi  [N_NODES];       // in-degree (edges only)
__device__ __align__(16) int   g_rowptr[N_NODES + 1];   // CSR row offsets
__device__ __align__(16) int   g_cursor[N_NODES];       // fill cursors
__device__ __align__(16) int   g_csrc  [N_EDGES];       // CSR src indices (dst-sorted)
__device__ __align__(16) int   g_bsum  [NBLK];          // per-block degree sums
__device__ __align__(16) int   g_bbase [NBLK];          // exclusive block bases
__device__ __align__(16) float g_dinv  [N_NODES];
__device__ __align__(16) float g_h1    [N_NODES * H1DIM];
__device__ __align__(16) float g_agg1  [N_NODES * H1DIM];
__device__ __align__(16) float g_h2    [N_NODES * H2DIM];
__device__ __align__(16) float g_agg2  [N_NODES * H2DIM];
__device__ __align__(16) float g_sum   [N_GRAPHS * H2DIM];
__device__ __align__(16) float g_cnt   [N_GRAPHS];
__device__ int g_ei64;    // 1 if edge_index is int64, else int32
__device__ int g_bat64;   // 1 if batch_index is int64, else int32

__device__ __forceinline__ int clampi(int v, int lo, int hi) {
    return v < lo ? lo : (v > hi ? hi : v);
}

// TF32 rounding (matches XLA/cuBLAS default f32 matmul precision on GPU)
__device__ __forceinline__ float tf32r(float v) {
    unsigned r;
    asm("cvt.rna.tf32.f32 %0, %1;" : "=r"(r) : "f"(v));
    return __uint_as_float(r);
}

// dtype-agnostic index load: i-th logical element of an index array
__device__ __forceinline__ int load_idx(const void* p, long long i, int is64) {
    if (is64) return (int)((const long long*)p)[i];
    return ((const int*)p)[i];
}

// ---------------- 0. probe dtypes of integer inputs -----------------------
// All probed 32-bit word indices are IN-BOUNDS for BOTH dtype interpretations.
__global__ void k_probe(const int* __restrict__ ei32, const int* __restrict__ bat32) {
    if (threadIdx.x == 0) {
        int all0 = 1;
        for (int k = 0; k < 64; k++) if (ei32[2 * k + 1] != 0) { all0 = 0; break; }
        g_ei64 = all0;
        int all0b = 1;
        for (int k = 40000; k < 40064; k++)
            if (bat32[2 * k + 1] != 0) { all0b = 0; break; }
        g_bat64 = all0b;
    }
}

// ---------------- 1. init: zero degree + pool accumulators ----------------
__global__ void k_init(void) {
    int i = blockIdx.x * blockDim.x + threadIdx.x;
    if (i < N_NODES) g_degi[i] = 0;
    if (i < N_GRAPHS * H2DIM) g_sum[i] = 0.0f;
    if (i < N_GRAPHS) g_cnt[i] = 0.0f;
}

// ---------------- 2. in-degree over edge dst (int atomics) ----------------
__global__ void k_deg(const void* __restrict__ ei) {
    int e = blockIdx.x * blockDim.x + threadIdx.x;
    int is64 = g_ei64;
    if (e < N_EDGES) {
        int d = clampi(load_idx(ei, (long long)N_EDGES + e, is64), 0, N_NODES - 1);
        atomicAdd(&g_degi[d], 1);
    }
}

// ---------------- 3a. per-block degree sums -------------------------------
__global__ void k_bsum(void) {
    __shared__ int swarp[SB / 32];
    int tid = threadIdx.x;
    int i = blockIdx.x * SB + tid;
    int v = (i < N_NODES) ? g_degi[i] : 0;
    // warp reduce
    for (int off = 16; off > 0; off >>= 1) v += __shfl_down_sync(0xffffffffu, v, off);
    if ((tid & 31) == 0) swarp[tid >> 5] = v;
    __syncthreads();
    if (tid < SB / 32) {
        int w = swarp[tid];
        for (int off = SB / 64; off > 0; off >>= 1) w += __shfl_down_sync(0xffffffffu, w, off);
        if (tid == 0) g_bsum[blockIdx.x] = w;
    }
}

// ---------------- 3b. scan the 98 block sums (1 tiny block) ---------------
__global__ void k_bscan(void) {
    __shared__ int s[128];
    int t = threadIdx.x;
    int v = (t < NBLK) ? g_bsum[t] : 0;
    s[t] = v;
    __syncthreads();
    for (int off = 1; off < 128; off <<= 1) {
        int u = (t >= off) ? s[t - off] : 0;
        __syncthreads();
        s[t] += u;
        __syncthreads();
    }
    if (t < NBLK) g_bbase[t] = s[t] - v;   // exclusive base
}

// ---------------- 3c. block-local scan + base -> rowptr, cursor -----------
__global__ void k_rowfill(void) {
    __shared__ int s[SB];
    int tid = threadIdx.x;
    int i = blockIdx.x * SB + tid;
    int v = (i < N_NODES) ? g_degi[i] : 0;
    s[tid] = v;
    __syncthreads();
    for (int off = 1; off < SB; off <<= 1) {
        int u = (tid >= off) ? s[tid - off] : 0;
        __syncthreads();
        s[tid] += u;
        __syncthreads();
    }
    int incl = s[tid];
    int base = g_bbase[blockIdx.x];
    if (i < N_NODES) {
        int r = base + incl - v;
        g_rowptr[i] = r;
        g_cursor[i] = r;
        if (i == N_NODES - 1) g_rowptr[N_NODES] = base + incl;
    }
}

// ---------------- 4. dinv = rsqrt(in-degree + self loop) ------------------
__global__ void k_dinv(void) {
    int i = blockIdx.x * blockDim.x + threadIdx.x;
    if (i < N_NODES) g_dinv[i] = rsqrtf((float)(g_degi[i] + 1));
}

// ---------------- 5. CSR fill: scatter src into dst buckets ---------------
__global__ void k_fill(const void* __restrict__ ei) {
    int e = blockIdx.x * blockDim.x + threadIdx.x;
    int is64 = g_ei64;
    if (e < N_EDGES) {
        int s = clampi(load_idx(ei, e, is64), 0, N_NODES - 1);
        int d = clampi(load_idx(ei, (long long)N_EDGES + e, is64), 0, N_NODES - 1);
        int pos = atomicAdd(&g_cursor[d], 1);
        g_csrc[clampi(pos, 0, N_EDGES - 1)] = s;
    }
}

// ---------------- 6. GEMM1: h1 = X @ W1   (warp per row, tf32 inputs) -----
__global__ void k_gemm1(const float* __restrict__ x, const float* __restrict__ W1) {
    __shared__ float sW[FEAT * H1DIM];           // 16 KB
    for (int i = threadIdx.x; i < FEAT * H1DIM; i += blockDim.x) sW[i] = tf32r(W1[i]);
    __syncthreads();
    int warp = threadIdx.x >> 5, lane = threadIdx.x & 31;
    int row = blockIdx.x * 8 + warp;
    if (row >= N_NODES) return;
    float4 xv = reinterpret_cast<const float4*>(x)[row * (FEAT / 4) + lane];
    xv.x = tf32r(xv.x); xv.y = tf32r(xv.y); xv.z = tf32r(xv.z); xv.w = tf32r(xv.w);
    float acc = 0.0f;
#pragma unroll
    for (int r = 0; r < 32; r++) {
        float bx = __shfl_sync(0xffffffffu, xv.x, r);
        float by = __shfl_sync(0xffffffffu, xv.y, r);
        float bz = __shfl_sync(0xffffffffu, xv.z, r);
        float bw = __shfl_sync(0xffffffffu, xv.w, r);
        int k = r * 4;
        acc = fmaf(bx, sW[(k + 0) * H1DIM + lane], acc);
        acc = fmaf(by, sW[(k + 1) * H1DIM + lane], acc);
        acc = fmaf(bz, sW[(k + 2) * H1DIM + lane], acc);
        acc = fmaf(bw, sW[(k + 3) * H1DIM + lane], acc);
    }
    g_h1[row * H1DIM + lane] = acc;
}

// ---------------- 7. agg1: warp-per-node gather (no atomics) --------------
__global__ void k_agg1(void) {
    int warp = (blockIdx.x * blockDim.x + threadIdx.x) >> 5;
    int lane = threadIdx.x & 31;
    if (warp >= N_NODES) return;
    int d = warp;
    int start = g_rowptr[d], end = g_rowptr[d + 1];
    float dvd = g_dinv[d];
    float acc = g_h1[d * H1DIM + lane] * dvd;
    for (int base = start; base < end; base += 32) {
        int n = end - base;
        int s = 0; float dvs = 0.0f;
        if (lane < n) { s = g_csrc[base + lane]; dvs = g_dinv[s]; }
        int m = n < 32 ? n : 32;
        for (int j = 0; j < m; j++) {
            int   sj = __shfl_sync(0xffffffffu, s,   j);
            float dj = __shfl_sync(0xffffffffu, dvs, j);
            acc = fmaf(g_h1[sj * H1DIM + lane], dj, acc);
        }
    }
    g_agg1[d * H1DIM + lane] = acc * dvd;
}

// ---------------- 8. fused bias1+relu + GEMM2 (tf32 inputs) ---------------
__global__ void k_gemm2(const float* __restrict__ b1, const float* __restrict__ W2) {
    __shared__ float sW[H1DIM * H2DIM];          // 2 KB
    __shared__ float sb[H1DIM];
    for (int i = threadIdx.x; i < H1DIM * H2DIM; i += blockDim.x) sW[i] = tf32r(W2[i]);
    if (threadIdx.x < H1DIM) sb[threadIdx.x] = b1[threadIdx.x];
    __syncthreads();
    int warp = threadIdx.x >> 5, lane = threadIdx.x & 31;
    int row = blockIdx.x * 8 + warp;
    if (row >= N_NODES) return;
    float v = g_agg1[row * H1DIM + lane] + sb[lane];
    v = tf32r(fmaxf(v, 0.0f));
    int j = lane & 15;
    float acc = 0.0f;
#pragma unroll
    for (int r = 0; r < 32; r++) {
        float xb = __shfl_sync(0xffffffffu, v, r);
        acc = fmaf(xb, sW[r * H2DIM + j], acc);
    }
    if (lane < H2DIM) g_h2[row * H2DIM + lane] = acc;
}

// ---------------- 9. agg2: warp-per-node gather (H2 = 16) -----------------
__global__ void k_agg2(void) {
    int warp = (blockIdx.x * blockDim.x + threadIdx.x) >> 5;
    int lane = threadIdx.x & 31;
    if (warp >= N_NODES) return;
    int d = warp;
    int start = g_rowptr[d], end = g_rowptr[d + 1];
    float dvd = g_dinv[d];
    float acc = (lane < H2DIM) ? g_h2[d * H2DIM + lane] * dvd : 0.0f;
    for (int base = start; base < end; base += 32) {
        int n = end - base;
        int s = 0; float dvs = 0.0f;
        if (lane < n) { s = g_csrc[base + lane]; dvs = g_dinv[s]; }
        int m = n < 32 ? n : 32;
        for (int j = 0; j < m; j++) {
            int   sj = __shfl_sync(0xffffffffu, s,   j);
            float dj = __shfl_sync(0xffffffffu, dvs, j);
            if (lane < H2DIM)
                acc = fmaf(g_h2[sj * H2DIM + lane], dj, acc);
        }
    }
    if (lane < H2DIM) g_agg2[d * H2DIM + lane] = acc * dvd;
}

// ---------------- 10. pool: relu(agg2+b2) -> per-graph sums (scalar) ------
__global__ void k_pool(const float* __restrict__ b2, const void* __restrict__ batch) {
    int idx = blockIdx.x * blockDim.x + threadIdx.x;
    int node = idx >> 4, c = idx & 15;
    int is64 = g_bat64;
    if (node >= N_NODES) return;
    int g = clampi(load_idx(batch, node, is64), 0, N_GRAPHS - 1);
    float v = fmaxf(g_agg2[node * H2DIM + c] + b2[c], 0.0f);
    atomicAdd(&g_sum[g * H2DIM + c], v);
    if (c == 0) atomicAdd(&g_cnt[g], 1.0f);
}

// ---------------- 11. final: mean, FC (tf32), softmax ---------------------
__global__ void k_final(const float* __restrict__ fc_w, const float* __restrict__ fc_b,
                        float* __restrict__ out) {
    int g = blockIdx.x * blockDim.x + threadIdx.x;
    if (g >= N_GRAPHS) return;
    float inv = 1.0f / fmaxf(g_cnt[g], 1.0f);
    float p[H2DIM];
#pragma unroll
    for (int j = 0; j < H2DIM; j++) p[j] = tf32r(g_sum[g * H2DIM + j] * inv);
    float logit[NCLS];
#pragma unroll
    for (int c = 0; c < NCLS; c++) {
        float acc = 0.0f;
#pragma unroll
        for (int j = 0; j < H2DIM; j++) acc = fmaf(p[j], tf32r(fc_w[j * NCLS + c]), acc);
        logit[c] = acc + fc_b[c];
    }
    float m = logit[0];
#pragma unroll
    for (int c = 1; c < NCLS; c++) m = fmaxf(m, logit[c]);
    float s = 0.0f;
#pragma unroll
    for (int c = 0; c < NCLS; c++) { logit[c] = expf(logit[c] - m); s += logit[c]; }
    float invs = 1.0f / s;
#pragma unroll
    for (int c = 0; c < NCLS; c++) out[g * NCLS + c] = logit[c] * invs;
}

// ---------------------------------------------------------------------------
extern "C" void kernel_launch(void* const* d_in, const int* in_sizes, int n_in,
                              void* d_out, int out_size) {
    // PRIMARY: positional binding in reference-dict order
    const float *x   = (n_in > 0) ? (const float*)d_in[0] : 0;
    const void  *ei  = (n_in > 1) ? d_in[1]               : 0;
    const void  *bat = (n_in > 2) ? d_in[2]               : 0;
    const float *W1  = (n_in > 3) ? (const float*)d_in[3] : 0;
    const float *b1  = (n_in > 4) ? (const float*)d_in[4] : 0;
    const float *W2  = (n_in > 5) ? (const float*)d_in[5] : 0;
    const float *b2  = (n_in > 6) ? (const float*)d_in[6] : 0;
    const float *fcw = (n_in > 7) ? (const float*)d_in[7] : 0;
    const float *fcb = (n_in > 8) ? (const float*)d_in[8] : 0;

    // SECONDARY: override by exact element-count match (all counts distinct).
    for (int i = 0; i < n_in; i++) {
        switch (in_sizes[i]) {
            case N_NODES * FEAT:   x   = (const float*)d_in[i]; break;  // 12.8M
            case 2 * N_EDGES:      ei  = d_in[i];               break;  // 6.4M
            case N_NODES:          bat = d_in[i];               break;  // 100k
            case FEAT * H1DIM:     W1  = (const float*)d_in[i]; break;  // 4096
            case H1DIM:            b1  = (const float*)d_in[i]; break;  // 32
            case H1DIM * H2DIM:    W2  = (const float*)d_in[i]; break;  // 512
            case H2DIM:            b2  = (const float*)d_in[i]; break;  // 16
            case H2DIM * NCLS:     fcw = (const float*)d_in[i]; break;  // 160
            case NCLS:             fcb = (const float*)d_in[i]; break;  // 10
            default: break;
        }
    }
    float* out = (float*)d_out;
    if (!x || !ei || !bat || !W1 || !b1 || !W2 || !b2 || !fcw || !fcb || !out) return;

    const int T = 256;
    k_probe  <<<1, 32>>>((const int*)ei, (const int*)bat);
    k_init   <<<(N_NODES + T - 1) / T, T>>>();
    k_deg    <<<(N_EDGES + T - 1) / T, T>>>(ei);
    k_bsum   <<<NBLK, SB>>>();
    k_bscan  <<<1, 128>>>();
    k_rowfill<<<NBLK, SB>>>();
    k_dinv   <<<(N_NODES + T - 1) / T, T>>>();
    k_fill   <<<(N_EDGES + T - 1) / T, T>>>(ei);
    k_gemm1  <<<(N_NODES + 7) / 8, T>>>(x, W1);
    k_agg1   <<<(N_NODES * 32 + T - 1) / T, T>>>();
    k_gemm2  <<<(N_NODES + 7) / 8, T>>>(b1, W2);
    k_agg2   <<<(N_NODES * 32 + T - 1) / T, T>>>();
    k_pool   <<<(N_NODES * H2DIM + T - 1) / T, T>>>(b2, bat);
    k_final  <<<(N_GRAPHS + T - 1) / T, T>>>(fcw, fcb, out);
}

// round 9
// speedup vs baseline: 1.4937x; 1.0747x over previous
#include <cuda_runtime.h>
#include <cuda_bf16.h>
#include <math.h>

#define N_NODES   100000
#define N_EDGES   3200000
#define N_GRAPHS  512
#define FEAT      128
#define H1DIM     32
#define H2DIM     16
#define NCLS      10

#define SB        1024                         // scan block size
#define NBLK      ((N_NODES + SB - 1) / SB)    // 98

// ---------------- scratch (device globals; no allocation allowed) ----------
__device__ __align__(16) int   g_degi  [N_NODES];       // in-degree (edges only)
__device__ __align__(16) int   g_rowptr[N_NODES + 1];   // CSR row offsets
__device__ __align__(16) int   g_cursor[N_NODES];       // fill cursors
__device__ __align__(16) int2  g_csr   [N_EDGES];       // {src, bitcast dinv[src]}
__device__ __align__(16) int   g_bsum  [NBLK];          // per-block degree sums
__device__ __align__(16) int   g_bbase [NBLK];          // exclusive block bases
__device__ __align__(16) float g_dinv  [N_NODES];
__device__ __align__(16) float g_h1    [N_NODES * H1DIM];
__device__ __align__(16) float g_h2    [N_NODES * H2DIM];
__device__ __align__(16) float g_sum   [N_GRAPHS * H2DIM];
__device__ __align__(16) float g_cnt   [N_GRAPHS];
__device__ int g_ei64;    // 1 if edge_index is int64, else int32
__device__ int g_bat64;   // 1 if batch_index is int64, else int32

__device__ __forceinline__ int clampi(int v, int lo, int hi) {
    return v < lo ? lo : (v > hi ? hi : v);
}

// TF32 rounding (matches XLA/cuBLAS default f32 matmul precision on GPU)
__device__ __forceinline__ float tf32r(float v) {
    unsigned r;
    asm("cvt.rna.tf32.f32 %0, %1;" : "=r"(r) : "f"(v));
    return __uint_as_float(r);
}

// dtype-agnostic index load: i-th logical element of an index array
__device__ __forceinline__ int load_idx(const void* p, long long i, int is64) {
    if (is64) return (int)((const long long*)p)[i];
    return ((const int*)p)[i];
}

// ---------------- 0. probe dtypes of integer inputs -----------------------
// All probed 32-bit word indices are IN-BOUNDS for BOTH dtype interpretations.
__global__ void k_probe(const int* __restrict__ ei32, const int* __restrict__ bat32) {
    if (threadIdx.x == 0) {
        int all0 = 1;
        for (int k = 0; k < 64; k++) if (ei32[2 * k + 1] != 0) { all0 = 0; break; }
        g_ei64 = all0;
        int all0b = 1;
        for (int k = 40000; k < 40064; k++)
            if (bat32[2 * k + 1] != 0) { all0b = 0; break; }
        g_bat64 = all0b;
    }
}

// ---------------- 1. init: zero degree + pool accumulators ----------------
__global__ void k_init(void) {
    int i = blockIdx.x * blockDim.x + threadIdx.x;
    if (i < N_NODES) g_degi[i] = 0;
    if (i < N_GRAPHS * H2DIM) g_sum[i] = 0.0f;
    if (i < N_GRAPHS) g_cnt[i] = 0.0f;
}

// ---------------- 2. in-degree over edge dst (int atomics) ----------------
__global__ void k_deg(const void* __restrict__ ei) {
    int e = blockIdx.x * blockDim.x + threadIdx.x;
    int is64 = g_ei64;
    if (e < N_EDGES) {
        int d = clampi(load_idx(ei, (long long)N_EDGES + e, is64), 0, N_NODES - 1);
        atomicAdd(&g_degi[d], 1);
    }
}

// ---------------- 3a. per-block degree sums -------------------------------
__global__ void k_bsum(void) {
    __shared__ int swarp[SB / 32];
    int tid = threadIdx.x;
    int i = blockIdx.x * SB + tid;
    int v = (i < N_NODES) ? g_degi[i] : 0;
    for (int off = 16; off > 0; off >>= 1) v += __shfl_down_sync(0xffffffffu, v, off);
    if ((tid & 31) == 0) swarp[tid >> 5] = v;
    __syncthreads();
    if (tid < SB / 32) {
        int w = swarp[tid];
        for (int off = SB / 64; off > 0; off >>= 1) w += __shfl_down_sync(0xffffffffu, w, off);
        if (tid == 0) g_bsum[blockIdx.x] = w;
    }
}

// ---------------- 3b. scan the 98 block sums (1 tiny block) ---------------
__global__ void k_bscan(void) {
    __shared__ int s[128];
    int t = threadIdx.x;
    int v = (t < NBLK) ? g_bsum[t] : 0;
    s[t] = v;
    __syncthreads();
    for (int off = 1; off < 128; off <<= 1) {
        int u = (t >= off) ? s[t - off] : 0;
        __syncthreads();
        s[t] += u;
        __syncthreads();
    }
    if (t < NBLK) g_bbase[t] = s[t] - v;   // exclusive base
}

// ---------------- 3c. block scan + base -> rowptr, cursor, dinv -----------
__global__ void k_rowfill(void) {
    __shared__ int s[SB];
    int tid = threadIdx.x;
    int i = blockIdx.x * SB + tid;
    int v = (i < N_NODES) ? g_degi[i] : 0;
    s[tid] = v;
    __syncthreads();
    for (int off = 1; off < SB; off <<= 1) {
        int u = (tid >= off) ? s[tid - off] : 0;
        __syncthreads();
        s[tid] += u;
        __syncthreads();
    }
    int incl = s[tid];
    int base = g_bbase[blockIdx.x];
    if (i < N_NODES) {
        int r = base + incl - v;
        g_rowptr[i] = r;
        g_cursor[i] = r;
        g_dinv[i]   = rsqrtf((float)(v + 1));
        if (i == N_NODES - 1) g_rowptr[N_NODES] = base + incl;
    }
}

// ---------------- 5. CSR fill: scatter {src, dinv[src]} -------------------
__global__ void k_fill(const void* __restrict__ ei) {
    int e = blockIdx.x * blockDim.x + threadIdx.x;
    int is64 = g_ei64;
    if (e < N_EDGES) {
        int s = clampi(load_idx(ei, e, is64), 0, N_NODES - 1);
        int d = clampi(load_idx(ei, (long long)N_EDGES + e, is64), 0, N_NODES - 1);
        int pos = atomicAdd(&g_cursor[d], 1);
        int2 pay;
        pay.x = s;
        pay.y = __float_as_int(g_dinv[s]);
        g_csr[clampi(pos, 0, N_EDGES - 1)] = pay;
    }
}

// ---------------- 6. GEMM1: h1 = X @ W1   (warp per row, tf32 inputs) -----
__global__ void k_gemm1(const float* __restrict__ x, const float* __restrict__ W1) {
    __shared__ float sW[FEAT * H1DIM];           // 16 KB
    for (int i = threadIdx.x; i < FEAT * H1DIM; i += blockDim.x) sW[i] = tf32r(W1[i]);
    __syncthreads();
    int warp = threadIdx.x >> 5, lane = threadIdx.x & 31;
    int row = blockIdx.x * 8 + warp;
    if (row >= N_NODES) return;
    float4 xv = reinterpret_cast<const float4*>(x)[row * (FEAT / 4) + lane];
    xv.x = tf32r(xv.x); xv.y = tf32r(xv.y); xv.z = tf32r(xv.z); xv.w = tf32r(xv.w);
    float acc = 0.0f;
#pragma unroll
    for (int r = 0; r < 32; r++) {
        float bx = __shfl_sync(0xffffffffu, xv.x, r);
        float by = __shfl_sync(0xffffffffu, xv.y, r);
        float bz = __shfl_sync(0xffffffffu, xv.z, r);
        float bw = __shfl_sync(0xffffffffu, xv.w, r);
        int k = r * 4;
        acc = fmaf(bx, sW[(k + 0) * H1DIM + lane], acc);
        acc = fmaf(by, sW[(k + 1) * H1DIM + lane], acc);
        acc = fmaf(bz, sW[(k + 2) * H1DIM + lane], acc);
        acc = fmaf(bw, sW[(k + 3) * H1DIM + lane], acc);
    }
    g_h1[row * H1DIM + lane] = acc;
}

// ------- 7. FUSED agg1 + bias1 + relu + GEMM2 -> h2 (warp per node) -------
__global__ void k_agg1g2(const float* __restrict__ b1, const float* __restrict__ W2) {
    __shared__ float sW[H1DIM * H2DIM];          // 2 KB
    __shared__ float sb[H1DIM];
    for (int i = threadIdx.x; i < H1DIM * H2DIM; i += blockDim.x) sW[i] = tf32r(W2[i]);
    if (threadIdx.x < H1DIM) sb[threadIdx.x] = b1[threadIdx.x];
    __syncthreads();
    int warp = (blockIdx.x * blockDim.x + threadIdx.x) >> 5;
    int lane = threadIdx.x & 31;
    if (warp >= N_NODES) return;
    int d = warp;
    int start = g_rowptr[d], end = g_rowptr[d + 1];
    float dvd = g_dinv[d];
    float acc = g_h1[d * H1DIM + lane] * dvd;     // self loop (dvd^2 after final mul)
    for (int base = start; base < end; base += 32) {
        int n = end - base;
        int s = 0; float dvs = 0.0f;
        if (lane < n) {
            int2 pay = g_csr[base + lane];
            s = pay.x; dvs = __int_as_float(pay.y);
        }
        int m = n < 32 ? n : 32;
#pragma unroll 4
        for (int j = 0; j < m; j++) {
            int   sj = __shfl_sync(0xffffffffu, s,   j);
            float dj = __shfl_sync(0xffffffffu, dvs, j);
            acc = fmaf(g_h1[sj * H1DIM + lane], dj, acc);
        }
    }
    // bias + relu + tf32, then GEMM2 row via shfl reduction
    float v = tf32r(fmaxf(acc * dvd + sb[lane], 0.0f));
    int j = lane & 15;
    float acc2 = 0.0f;
#pragma unroll
    for (int r = 0; r < 32; r++) {
        float xb = __shfl_sync(0xffffffffu, v, r);
        acc2 = fmaf(xb, sW[r * H2DIM + j], acc2);
    }
    if (lane < H2DIM) g_h2[d * H2DIM + lane] = acc2;
}

// ------- 8. FUSED agg2 + bias2 + relu + pool scatter (warp per node) ------
__global__ void k_agg2pool(const float* __restrict__ b2, const void* __restrict__ batch) {
    int warp = (blockIdx.x * blockDim.x + threadIdx.x) >> 5;
    int lane = threadIdx.x & 31;
    int is64 = g_bat64;
    if (warp >= N_NODES) return;
    int d = warp;
    int start = g_rowptr[d], end = g_rowptr[d + 1];
    float dvd = g_dinv[d];
    float acc = (lane < H2DIM) ? g_h2[d * H2DIM + lane] * dvd : 0.0f;
    for (int base = start; base < end; base += 32) {
        int n = end - base;
        int s = 0; float dvs = 0.0f;
        if (lane < n) {
            int2 pay = g_csr[base + lane];
            s = pay.x; dvs = __int_as_float(pay.y);
        }
        int m = n < 32 ? n : 32;
#pragma unroll 4
        for (int j = 0; j < m; j++) {
            int   sj = __shfl_sync(0xffffffffu, s,   j);
            float dj = __shfl_sync(0xffffffffu, dvs, j);
            if (lane < H2DIM)
                acc = fmaf(g_h2[sj * H2DIM + lane], dj, acc);
        }
    }
    int g = clampi(load_idx(batch, d, is64), 0, N_GRAPHS - 1);
    if (lane < H2DIM) {
        float v = fmaxf(acc * dvd + b2[lane], 0.0f);
        atomicAdd(&g_sum[g * H2DIM + lane], v);
    } else if (lane == H2DIM) {
        atomicAdd(&g_cnt[g], 1.0f);
    }
}

// ---------------- 11. final: mean, FC (tf32), softmax ---------------------
__global__ void k_final(const float* __restrict__ fc_w, const float* __restrict__ fc_b,
                        float* __restrict__ out) {
    int g = blockIdx.x * blockDim.x + threadIdx.x;
    if (g >= N_GRAPHS) return;
    float inv = 1.0f / fmaxf(g_cnt[g], 1.0f);
    float p[H2DIM];
#pragma unroll
    for (int j = 0; j < H2DIM; j++) p[j] = tf32r(g_sum[g * H2DIM + j] * inv);
    float logit[NCLS];
#pragma unroll
    for (int c = 0; c < NCLS; c++) {
        float acc = 0.0f;
#pragma unroll
        for (int j = 0; j < H2DIM; j++) acc = fmaf(p[j], tf32r(fc_w[j * NCLS + c]), acc);
        logit[c] = acc + fc_b[c];
    }
    float m = logit[0];
#pragma unroll
    for (int c = 1; c < NCLS; c++) m = fmaxf(m, logit[c]);
    float s = 0.0f;
#pragma unroll
    for (int c = 0; c < NCLS; c++) { logit[c] = expf(logit[c] - m); s += logit[c]; }
    float invs = 1.0f / s;
#pragma unroll
    for (int c = 0; c < NCLS; c++) out[g * NCLS + c] = logit[c] * invs;
}

// ---------------------------------------------------------------------------
extern "C" void kernel_launch(void* const* d_in, const int* in_sizes, int n_in,
                              void* d_out, int out_size) {
    // PRIMARY: positional binding in reference-dict order
    const float *x   = (n_in > 0) ? (const float*)d_in[0] : 0;
    const void  *ei  = (n_in > 1) ? d_in[1]               : 0;
    const void  *bat = (n_in > 2) ? d_in[2]               : 0;
    const float *W1  = (n_in > 3) ? (const float*)d_in[3] : 0;
    const float *b1  = (n_in > 4) ? (const float*)d_in[4] : 0;
    const float *W2  = (n_in > 5) ? (const float*)d_in[5] : 0;
    const float *b2  = (n_in > 6) ? (const float*)d_in[6] : 0;
    const float *fcw = (n_in > 7) ? (const float*)d_in[7] : 0;
    const float *fcb = (n_in > 8) ? (const float*)d_in[8] : 0;

    // SECONDARY: override by exact element-count match (all counts distinct).
    for (int i = 0; i < n_in; i++) {
        switch (in_sizes[i]) {
            case N_NODES * FEAT:   x   = (const float*)d_in[i]; break;  // 12.8M
            case 2 * N_EDGES:      ei  = d_in[i];               break;  // 6.4M
            case N_NODES:          bat = d_in[i];               break;  // 100k
            case FEAT * H1DIM:     W1  = (const float*)d_in[i]; break;  // 4096
            case H1DIM:            b1  = (const float*)d_in[i]; break;  // 32
            case H1DIM * H2DIM:    W2  = (const float*)d_in[i]; break;  // 512
            case H2DIM:            b2  = (const float*)d_in[i]; break;  // 16
            case H2DIM * NCLS:     fcw = (const float*)d_in[i]; break;  // 160
            case NCLS:             fcb = (const float*)d_in[i]; break;  // 10
            default: break;
        }
    }
    float* out = (float*)d_out;
    if (!x || !ei || !bat || !W1 || !b1 || !W2 || !b2 || !fcw || !fcb || !out) return;

    const int T = 256;
    k_probe   <<<1, 32>>>((const int*)ei, (const int*)bat);
    k_init    <<<(N_NODES + T - 1) / T, T>>>();
    k_deg     <<<(N_EDGES + T - 1) / T, T>>>(ei);
    k_bsum    <<<NBLK, SB>>>();
    k_bscan   <<<1, 128>>>();
    k_rowfill <<<NBLK, SB>>>();
    k_fill    <<<(N_EDGES + T - 1) / T, T>>>(ei);
    k_gemm1   <<<(N_NODES + 7) / 8, T>>>(x, W1);
    k_agg1g2  <<<(N_NODES * 32 + T - 1) / T, T>>>(b1, W2);
    k_agg2pool<<<(N_NODES * 32 + T - 1) / T, T>>>(b2, bat);
    k_final   <<<(N_GRAPHS + T - 1) / T, T>>>(fcw, fcb, out);
}

// round 10
// speedup vs baseline: 1.8169x; 1.2163x over previous
#include <cuda_runtime.h>
#include <cuda_bf16.h>
#include <math.h>

#define N_NODES   100000
#define N_EDGES   3200000
#define N_GRAPHS  512
#define FEAT      128
#define H1DIM     32
#define H2DIM     16
#define NCLS      10

#define SB        1024
#define NBLK      ((N_NODES + SB - 1) / SB)    // 98

#define G1ROWS    32                            // gemm1 tile rows
#define G1PAD     132                           // padded row stride (floats)

// ---------------- scratch ---------------------------------------------------
__device__ __align__(16) int   g_degi  [N_NODES];
__device__ __align__(16) int   g_rowptr[N_NODES + 1];
__device__ __align__(16) int   g_cursor[N_NODES];
__device__ __align__(16) int   g_csrc  [N_EDGES];        // src only (dst-sorted)
__device__ __align__(16) int   g_bsum  [NBLK];
__device__ __align__(16) int   g_bbase [NBLK];
__device__ __align__(16) float g_dinv  [N_NODES];
__device__ __align__(16) float g_h1s   [N_NODES * H1DIM]; // h1 * dinv (pre-scaled)
__device__ __align__(16) float g_h2s   [N_NODES * H2DIM]; // h2 * dinv (pre-scaled)
__device__ __align__(16) float g_sum   [N_GRAPHS * H2DIM];
__device__ __align__(16) float g_cnt   [N_GRAPHS];
__device__ int g_ei64;
__device__ int g_bat64;

__device__ __forceinline__ int clampi(int v, int lo, int hi) {
    return v < lo ? lo : (v > hi ? hi : v);
}

__device__ __forceinline__ float tf32r(float v) {
    unsigned r;
    asm("cvt.rna.tf32.f32 %0, %1;" : "=r"(r) : "f"(v));
    return __uint_as_float(r);
}

__device__ __forceinline__ int load_idx(const void* p, long long i, int is64) {
    if (is64) return (int)((const long long*)p)[i];
    return ((const int*)p)[i];
}

// ---------------- 0. probe dtypes ------------------------------------------
__global__ void k_probe(const int* __restrict__ ei32, const int* __restrict__ bat32) {
    if (threadIdx.x == 0) {
        int all0 = 1;
        for (int k = 0; k < 64; k++) if (ei32[2 * k + 1] != 0) { all0 = 0; break; }
        g_ei64 = all0;
        int all0b = 1;
        for (int k = 40000; k < 40064; k++)
            if (bat32[2 * k + 1] != 0) { all0b = 0; break; }
        g_bat64 = all0b;
    }
}

// ---------------- 1. init --------------------------------------------------
__global__ void k_init(void) {
    int i = blockIdx.x * blockDim.x + threadIdx.x;
    if (i < N_NODES) g_degi[i] = 0;
    if (i < N_GRAPHS * H2DIM) g_sum[i] = 0.0f;
    if (i < N_GRAPHS) g_cnt[i] = 0.0f;
}

// ---------------- 2. in-degree ---------------------------------------------
__global__ void k_deg(const void* __restrict__ ei) {
    int e = blockIdx.x * blockDim.x + threadIdx.x;
    int is64 = g_ei64;
    if (e < N_EDGES) {
        int d = clampi(load_idx(ei, (long long)N_EDGES + e, is64), 0, N_NODES - 1);
        atomicAdd(&g_degi[d], 1);
    }
}

// ---------------- 3a. block sums -------------------------------------------
__global__ void k_bsum(void) {
    __shared__ int swarp[SB / 32];
    int tid = threadIdx.x;
    int i = blockIdx.x * SB + tid;
    int v = (i < N_NODES) ? g_degi[i] : 0;
    for (int off = 16; off > 0; off >>= 1) v += __shfl_down_sync(0xffffffffu, v, off);
    if ((tid & 31) == 0) swarp[tid >> 5] = v;
    __syncthreads();
    if (tid < SB / 32) {
        int w = swarp[tid];
        for (int off = SB / 64; off > 0; off >>= 1) w += __shfl_down_sync(0xffffffffu, w, off);
        if (tid == 0) g_bsum[blockIdx.x] = w;
    }
}

// ---------------- 3b. scan block sums --------------------------------------
__global__ void k_bscan(void) {
    __shared__ int s[128];
    int t = threadIdx.x;
    int v = (t < NBLK) ? g_bsum[t] : 0;
    s[t] = v;
    __syncthreads();
    for (int off = 1; off < 128; off <<= 1) {
        int u = (t >= off) ? s[t - off] : 0;
        __syncthreads();
        s[t] += u;
        __syncthreads();
    }
    if (t < NBLK) g_bbase[t] = s[t] - v;
}

// ---------------- 3c. rowptr + cursor + dinv -------------------------------
__global__ void k_rowfill(void) {
    __shared__ int s[SB];
    int tid = threadIdx.x;
    int i = blockIdx.x * SB + tid;
    int v = (i < N_NODES) ? g_degi[i] : 0;
    s[tid] = v;
    __syncthreads();
    for (int off = 1; off < SB; off <<= 1) {
        int u = (tid >= off) ? s[tid - off] : 0;
        __syncthreads();
        s[tid] += u;
        __syncthreads();
    }
    int incl = s[tid];
    int base = g_bbase[blockIdx.x];
    if (i < N_NODES) {
        int r = base + incl - v;
        g_rowptr[i] = r;
        g_cursor[i] = r;
        g_dinv[i]   = rsqrtf((float)(v + 1));
        if (i == N_NODES - 1) g_rowptr[N_NODES] = base + incl;
    }
}

// ---------------- 5. CSR fill: src only ------------------------------------
__global__ void k_fill(const void* __restrict__ ei) {
    int e = blockIdx.x * blockDim.x + threadIdx.x;
    int is64 = g_ei64;
    if (e < N_EDGES) {
        int s = clampi(load_idx(ei, e, is64), 0, N_NODES - 1);
        int d = clampi(load_idx(ei, (long long)N_EDGES + e, is64), 0, N_NODES - 1);
        int pos = atomicAdd(&g_cursor[d], 1);
        g_csrc[clampi(pos, 0, N_EDGES - 1)] = s;
    }
}

// ------- 6. GEMM1 tiled: h1s = (X @ W1) * dinv  (thread = 4 outputs) -------
// Block: 256 threads, 32 rows. smem: X tile + W1^T, both padded stride 132.
__global__ void k_gemm1(const float* __restrict__ x, const float* __restrict__ W1) {
    __shared__ float sX [G1ROWS * G1PAD];   // 16.5 KB
    __shared__ float sWT[H1DIM * G1PAD];    // 16.5 KB
    int tid = threadIdx.x;
    int rowBase = blockIdx.x * G1ROWS;
    // W1^T: sWT[j][k] = W1[k][j]
    for (int i = tid; i < FEAT * H1DIM; i += 256) {
        int k = i >> 5, j = i & 31;
        sWT[j * G1PAD + k] = tf32r(W1[i]);
    }
    // X tile (float4 loads)
    for (int q = tid; q < G1ROWS * (FEAT / 4); q += 256) {
        int row = q >> 5, kq = q & 31;
        float4 v = reinterpret_cast<const float4*>(x)[(rowBase + row) * (FEAT / 4) + kq];
        v.x = tf32r(v.x); v.y = tf32r(v.y); v.z = tf32r(v.z); v.w = tf32r(v.w);
        *reinterpret_cast<float4*>(&sX[row * G1PAD + kq * 4]) = v;
    }
    __syncthreads();
    int r  = tid >> 3;        // 0..31 tile row
    int jg = tid & 7;         // col group: cols jg, jg+8, jg+16, jg+24
    float a0 = 0.f, a1 = 0.f, a2 = 0.f, a3 = 0.f;
    const float* xr = &sX[r * G1PAD];
    const float* w0 = &sWT[jg * G1PAD];
    const float* w1 = &sWT[(jg + 8) * G1PAD];
    const float* w2 = &sWT[(jg + 16) * G1PAD];
    const float* w3 = &sWT[(jg + 24) * G1PAD];
#pragma unroll
    for (int kq = 0; kq < FEAT / 4; kq++) {
        float4 xv = *reinterpret_cast<const float4*>(&xr[kq * 4]);
        float4 q0 = *reinterpret_cast<const float4*>(&w0[kq * 4]);
        float4 q1 = *reinterpret_cast<const float4*>(&w1[kq * 4]);
        float4 q2 = *reinterpret_cast<const float4*>(&w2[kq * 4]);
        float4 q3 = *reinterpret_cast<const float4*>(&w3[kq * 4]);
        a0 = fmaf(xv.x, q0.x, a0); a0 = fmaf(xv.y, q0.y, a0);
        a0 = fmaf(xv.z, q0.z, a0); a0 = fmaf(xv.w, q0.w, a0);
        a1 = fmaf(xv.x, q1.x, a1); a1 = fmaf(xv.y, q1.y, a1);
        a1 = fmaf(xv.z, q1.z, a1); a1 = fmaf(xv.w, q1.w, a1);
        a2 = fmaf(xv.x, q2.x, a2); a2 = fmaf(xv.y, q2.y, a2);
        a2 = fmaf(xv.z, q2.z, a2); a2 = fmaf(xv.w, q2.w, a2);
        a3 = fmaf(xv.x, q3.x, a3); a3 = fmaf(xv.y, q3.y, a3);
        a3 = fmaf(xv.z, q3.z, a3); a3 = fmaf(xv.w, q3.w, a3);
    }
    int row = rowBase + r;
    float dv = g_dinv[row];
    float* dst = &g_h1s[row * H1DIM];
    dst[jg]      = a0 * dv;
    dst[jg + 8]  = a1 * dv;
    dst[jg + 16] = a2 * dv;
    dst[jg + 24] = a3 * dv;
}

// ------- 7. FUSED agg1 + bias1 + relu + GEMM2 -> h2s (warp per node) -------
__global__ void k_agg1g2(const float* __restrict__ b1, const float* __restrict__ W2) {
    __shared__ float sW[H1DIM * H2DIM];
    __shared__ float sb[H1DIM];
    for (int i = threadIdx.x; i < H1DIM * H2DIM; i += blockDim.x) sW[i] = tf32r(W2[i]);
    if (threadIdx.x < H1DIM) sb[threadIdx.x] = b1[threadIdx.x];
    __syncthreads();
    int warp = (blockIdx.x * blockDim.x + threadIdx.x) >> 5;
    int lane = threadIdx.x & 31;
    if (warp >= N_NODES) return;
    int d = warp;
    int start = g_rowptr[d], end = g_rowptr[d + 1];
    float dvd = g_dinv[d];
    float acc = g_h1s[d * H1DIM + lane];          // self loop (pre-scaled)
    for (int base = start; base < end; base += 32) {
        int n = end - base;
        int s = 0;
        if (lane < n) s = g_csrc[base + lane];
        int m = n < 32 ? n : 32;
#pragma unroll 8
        for (int j = 0; j < m; j++) {
            int sj = __shfl_sync(0xffffffffu, s, j);
            acc += g_h1s[sj * H1DIM + lane];
        }
    }
    float v = tf32r(fmaxf(acc * dvd + sb[lane], 0.0f));
    int j = lane & 15;
    float acc2 = 0.0f;
#pragma unroll
    for (int r = 0; r < 32; r++) {
        float xb = __shfl_sync(0xffffffffu, v, r);
        acc2 = fmaf(xb, sW[r * H2DIM + j], acc2);
    }
    if (lane < H2DIM) g_h2s[d * H2DIM + lane] = acc2 * dvd;   // pre-scale for layer 2
}

// ------- 8. FUSED agg2 + bias2 + relu + pool scatter (warp per node) -------
__global__ void k_agg2pool(const float* __restrict__ b2, const void* __restrict__ batch) {
    int warp = (blockIdx.x * blockDim.x + threadIdx.x) >> 5;
    int lane = threadIdx.x & 31;
    int is64 = g_bat64;
    if (warp >= N_NODES) return;
    int d = warp;
    int start = g_rowptr[d], end = g_rowptr[d + 1];
    float dvd = g_dinv[d];
    float acc = (lane < H2DIM) ? g_h2s[d * H2DIM + lane] : 0.0f;
    for (int base = start; base < end; base += 32) {
        int n = end - base;
        int s = 0;
        if (lane < n) s = g_csrc[base + lane];
        int m = n < 32 ? n : 32;
#pragma unroll 8
        for (int j = 0; j < m; j++) {
            int sj = __shfl_sync(0xffffffffu, s, j);
            if (lane < H2DIM)
                acc += g_h2s[sj * H2DIM + lane];
        }
    }
    int g = clampi(load_idx(batch, d, is64), 0, N_GRAPHS - 1);
    if (lane < H2DIM) {
        float v = fmaxf(acc * dvd + b2[lane], 0.0f);
        atomicAdd(&g_sum[g * H2DIM + lane], v);
    } else if (lane == H2DIM) {
        atomicAdd(&g_cnt[g], 1.0f);
    }
}

// ---------------- 11. final: mean, FC (tf32), softmax ----------------------
__global__ void k_final(const float* __restrict__ fc_w, const float* __restrict__ fc_b,
                        float* __restrict__ out) {
    int g = blockIdx.x * blockDim.x + threadIdx.x;
    if (g >= N_GRAPHS) return;
    float inv = 1.0f / fmaxf(g_cnt[g], 1.0f);
    float p[H2DIM];
#pragma unroll
    for (int j = 0; j < H2DIM; j++) p[j] = tf32r(g_sum[g * H2DIM + j] * inv);
    float logit[NCLS];
#pragma unroll
    for (int c = 0; c < NCLS; c++) {
        float acc = 0.0f;
#pragma unroll
        for (int j = 0; j < H2DIM; j++) acc = fmaf(p[j], tf32r(fc_w[j * NCLS + c]), acc);
        logit[c] = acc + fc_b[c];
    }
    float m = logit[0];
#pragma unroll
    for (int c = 1; c < NCLS; c++) m = fmaxf(m, logit[c]);
    float s = 0.0f;
#pragma unroll
    for (int c = 0; c < NCLS; c++) { logit[c] = expf(logit[c] - m); s += logit[c]; }
    float invs = 1.0f / s;
#pragma unroll
    for (int c = 0; c < NCLS; c++) out[g * NCLS + c] = logit[c] * invs;
}

// ---------------------------------------------------------------------------
extern "C" void kernel_launch(void* const* d_in, const int* in_sizes, int n_in,
                              void* d_out, int out_size) {
    const float *x   = (n_in > 0) ? (const float*)d_in[0] : 0;
    const void  *ei  = (n_in > 1) ? d_in[1]               : 0;
    const void  *bat = (n_in > 2) ? d_in[2]               : 0;
    const float *W1  = (n_in > 3) ? (const float*)d_in[3] : 0;
    const float *b1  = (n_in > 4) ? (const float*)d_in[4] : 0;
    const float *W2  = (n_in > 5) ? (const float*)d_in[5] : 0;
    const float *b2  = (n_in > 6) ? (const float*)d_in[6] : 0;
    const float *fcw = (n_in > 7) ? (const float*)d_in[7] : 0;
    const float *fcb = (n_in > 8) ? (const float*)d_in[8] : 0;

    for (int i = 0; i < n_in; i++) {
        switch (in_sizes[i]) {
            case N_NODES * FEAT:   x   = (const float*)d_in[i]; break;
            case 2 * N_EDGES:      ei  = d_in[i];               break;
            case N_NODES:          bat = d_in[i];               break;
            case FEAT * H1DIM:     W1  = (const float*)d_in[i]; break;
            case H1DIM:            b1  = (const float*)d_in[i]; break;
            case H1DIM * H2DIM:    W2  = (const float*)d_in[i]; break;
            case H2DIM:            b2  = (const float*)d_in[i]; break;
            case H2DIM * NCLS:     fcw = (const float*)d_in[i]; break;
            case NCLS:             fcb = (const float*)d_in[i]; break;
            default: break;
        }
    }
    float* out = (float*)d_out;
    if (!x || !ei || !bat || !W1 || !b1 || !W2 || !b2 || !fcw || !fcb || !out) return;

    const int T = 256;
    k_probe   <<<1, 32>>>((const int*)ei, (const int*)bat);
    k_init    <<<(N_NODES + T - 1) / T, T>>>();
    k_deg     <<<(N_EDGES + T - 1) / T, T>>>(ei);
    k_bsum    <<<NBLK, SB>>>();
    k_bscan   <<<1, 128>>>();
    k_rowfill <<<NBLK, SB>>>();
    k_fill    <<<(N_EDGES + T - 1) / T, T>>>(ei);
    k_gemm1   <<<N_NODES / G1ROWS, 256>>>(x, W1);
    k_agg1g2  <<<(N_NODES * 32 + T - 1) / T, T>>>(b1, W2);
    k_agg2pool<<<(N_NODES * 32 + T - 1) / T, T>>>(b2, bat);
    k_final   <<<(N_GRAPHS + T - 1) / T, T>>>(fcw, fcb, out);
}

// round 11
// speedup vs baseline: 1.9734x; 1.0862x over previous
#include <cuda_runtime.h>
#include <cuda_bf16.h>
#include <math.h>

#define N_NODES   100000
#define N_EDGES   3200000
#define N_GRAPHS  512
#define FEAT      128
#define H1DIM     32
#define H2DIM     16
#define NCLS      10

#define SB        1024
#define NBLK      ((N_NODES + SB - 1) / SB)    // 98

#define G1ROWS    32                            // gemm1 tile rows
#define G1PAD     132                           // padded row stride (floats)

// ---------------- scratch ---------------------------------------------------
__device__ __align__(16)  int   g_degi  [N_NODES];
__device__ __align__(16)  int   g_rowptr[N_NODES + 1];
__device__ __align__(16)  int   g_cursor[N_NODES];
__device__ __align__(16)  int   g_csrc  [N_EDGES];        // src only (dst-sorted)
__device__ __align__(16)  int   g_bsum  [NBLK];
__device__ __align__(16)  int   g_bbase [NBLK];
__device__ __align__(16)  float g_dinv  [N_NODES];
__device__ __align__(128) float g_h1s   [N_NODES * H1DIM]; // h1 * dinv (row = one 128B line)
__device__ __align__(128) float g_h2s   [N_NODES * H2DIM]; // h2 * dinv (row = 64B)
__device__ __align__(16)  float g_sum   [N_GRAPHS * H2DIM];
__device__ __align__(16)  float g_cnt   [N_GRAPHS];
__device__ int g_ei64;
__device__ int g_bat64;

__device__ __forceinline__ int clampi(int v, int lo, int hi) {
    return v < lo ? lo : (v > hi ? hi : v);
}

__device__ __forceinline__ float tf32r(float v) {
    unsigned r;
    asm("cvt.rna.tf32.f32 %0, %1;" : "=r"(r) : "f"(v));
    return __uint_as_float(r);
}

__device__ __forceinline__ int load_idx(const void* p, long long i, int is64) {
    if (is64) return (int)((const long long*)p)[i];
    return ((const int*)p)[i];
}

// ---------------- 0. probe dtypes ------------------------------------------
__global__ void k_probe(const int* __restrict__ ei32, const int* __restrict__ bat32) {
    if (threadIdx.x == 0) {
        int all0 = 1;
        for (int k = 0; k < 64; k++) if (ei32[2 * k + 1] != 0) { all0 = 0; break; }
        g_ei64 = all0;
        int all0b = 1;
        for (int k = 40000; k < 40064; k++)
            if (bat32[2 * k + 1] != 0) { all0b = 0; break; }
        g_bat64 = all0b;
    }
}

// ---------------- 1. init --------------------------------------------------
__global__ void k_init(void) {
    int i = blockIdx.x * blockDim.x + threadIdx.x;
    if (i < N_NODES) g_degi[i] = 0;
    if (i < N_GRAPHS * H2DIM) g_sum[i] = 0.0f;
    if (i < N_GRAPHS) g_cnt[i] = 0.0f;
}

// ---------------- 2. in-degree ---------------------------------------------
__global__ void k_deg(const void* __restrict__ ei) {
    int e = blockIdx.x * blockDim.x + threadIdx.x;
    int is64 = g_ei64;
    if (e < N_EDGES) {
        int d = clampi(load_idx(ei, (long long)N_EDGES + e, is64), 0, N_NODES - 1);
        atomicAdd(&g_degi[d], 1);
    }
}

// ---------------- 3a. block sums -------------------------------------------
__global__ void k_bsum(void) {
    __shared__ int swarp[SB / 32];
    int tid = threadIdx.x;
    int i = blockIdx.x * SB + tid;
    int v = (i < N_NODES) ? g_degi[i] : 0;
    for (int off = 16; off > 0; off >>= 1) v += __shfl_down_sync(0xffffffffu, v, off);
    if ((tid & 31) == 0) swarp[tid >> 5] = v;
    __syncthreads();
    if (tid < SB / 32) {
        int w = swarp[tid];
        for (int off = SB / 64; off > 0; off >>= 1) w += __shfl_down_sync(0xffffffffu, w, off);
        if (tid == 0) g_bsum[blockIdx.x] = w;
    }
}

// ---------------- 3b. scan block sums --------------------------------------
__global__ void k_bscan(void) {
    __shared__ int s[128];
    int t = threadIdx.x;
    int v = (t < NBLK) ? g_bsum[t] : 0;
    s[t] = v;
    __syncthreads();
    for (int off = 1; off < 128; off <<= 1) {
        int u = (t >= off) ? s[t - off] : 0;
        __syncthreads();
        s[t] += u;
        __syncthreads();
    }
    if (t < NBLK) g_bbase[t] = s[t] - v;
}

// ---------- 3c. rowptr + cursor + dinv (warp-shuffle scan, 2 syncs) --------
__global__ void k_rowfill(void) {
    __shared__ int swsum[SB / 32];
    int tid  = threadIdx.x;
    int lane = tid & 31, wid = tid >> 5;
    int i = blockIdx.x * SB + tid;
    int v = (i < N_NODES) ? g_degi[i] : 0;
    // warp inclusive scan
    int incl = v;
    for (int off = 1; off < 32; off <<= 1) {
        int u = __shfl_up_sync(0xffffffffu, incl, off);
        if (lane >= off) incl += u;
    }
    if (lane == 31) swsum[wid] = incl;
    __syncthreads();
    if (wid == 0) {
        int w = (lane < SB / 32) ? swsum[lane] : 0;
        for (int off = 1; off < 32; off <<= 1) {
            int u = __shfl_up_sync(0xffffffffu, w, off);
            if (lane >= off) w += u;
        }
        if (lane < SB / 32) swsum[lane] = w;
    }
    __syncthreads();
    int warpBase = (wid == 0) ? 0 : swsum[wid - 1];
    int base = g_bbase[blockIdx.x];
    if (i < N_NODES) {
        int r = base + warpBase + incl - v;
        g_rowptr[i] = r;
        g_cursor[i] = r;
        g_dinv[i]   = rsqrtf((float)(v + 1));
        if (i == N_NODES - 1) g_rowptr[N_NODES] = base + warpBase + incl;
    }
}

// ---------------- 5. CSR fill: src only ------------------------------------
__global__ void k_fill(const void* __restrict__ ei) {
    int e = blockIdx.x * blockDim.x + threadIdx.x;
    int is64 = g_ei64;
    if (e < N_EDGES) {
        int s = clampi(load_idx(ei, e, is64), 0, N_NODES - 1);
        int d = clampi(load_idx(ei, (long long)N_EDGES + e, is64), 0, N_NODES - 1);
        int pos = atomicAdd(&g_cursor[d], 1);
        g_csrc[clampi(pos, 0, N_EDGES - 1)] = s;
    }
}

// ------- 6. GEMM1 tiled: h1s = (X @ W1) * dinv  (thread = 4 outputs) -------
__global__ void k_gemm1(const float* __restrict__ x, const float* __restrict__ W1) {
    __shared__ float sX [G1ROWS * G1PAD];   // 16.5 KB
    __shared__ float sWT[H1DIM * G1PAD];    // 16.5 KB
    int tid = threadIdx.x;
    int rowBase = blockIdx.x * G1ROWS;
    for (int i = tid; i < FEAT * H1DIM; i += 256) {
        int k = i >> 5, j = i & 31;
        sWT[j * G1PAD + k] = tf32r(W1[i]);
    }
    for (int q = tid; q < G1ROWS * (FEAT / 4); q += 256) {
        int row = q >> 5, kq = q & 31;
        float4 v = reinterpret_cast<const float4*>(x)[(rowBase + row) * (FEAT / 4) + kq];
        v.x = tf32r(v.x); v.y = tf32r(v.y); v.z = tf32r(v.z); v.w = tf32r(v.w);
        *reinterpret_cast<float4*>(&sX[row * G1PAD + kq * 4]) = v;
    }
    __syncthreads();
    int r  = tid >> 3;
    int jg = tid & 7;
    float a0 = 0.f, a1 = 0.f, a2 = 0.f, a3 = 0.f;
    const float* xr = &sX[r * G1PAD];
    const float* w0 = &sWT[jg * G1PAD];
    const float* w1 = &sWT[(jg + 8) * G1PAD];
    const float* w2 = &sWT[(jg + 16) * G1PAD];
    const float* w3 = &sWT[(jg + 24) * G1PAD];
#pragma unroll
    for (int kq = 0; kq < FEAT / 4; kq++) {
        float4 xv = *reinterpret_cast<const float4*>(&xr[kq * 4]);
        float4 q0 = *reinterpret_cast<const float4*>(&w0[kq * 4]);
        float4 q1 = *reinterpret_cast<const float4*>(&w1[kq * 4]);
        float4 q2 = *reinterpret_cast<const float4*>(&w2[kq * 4]);
        float4 q3 = *reinterpret_cast<const float4*>(&w3[kq * 4]);
        a0 = fmaf(xv.x, q0.x, a0); a0 = fmaf(xv.y, q0.y, a0);
        a0 = fmaf(xv.z, q0.z, a0); a0 = fmaf(xv.w, q0.w, a0);
        a1 = fmaf(xv.x, q1.x, a1); a1 = fmaf(xv.y, q1.y, a1);
        a1 = fmaf(xv.z, q1.z, a1); a1 = fmaf(xv.w, q1.w, a1);
        a2 = fmaf(xv.x, q2.x, a2); a2 = fmaf(xv.y, q2.y, a2);
        a2 = fmaf(xv.z, q2.z, a2); a2 = fmaf(xv.w, q2.w, a2);
        a3 = fmaf(xv.x, q3.x, a3); a3 = fmaf(xv.y, q3.y, a3);
        a3 = fmaf(xv.z, q3.z, a3); a3 = fmaf(xv.w, q3.w, a3);
    }
    int row = rowBase + r;
    float dv = g_dinv[row];
    float* dst = &g_h1s[row * H1DIM];
    dst[jg]      = a0 * dv;
    dst[jg + 8]  = a1 * dv;
    dst[jg + 16] = a2 * dv;
    dst[jg + 24] = a3 * dv;
}

// ------- 7. FUSED agg1 + bias1 + relu + GEMM2 -> h2s (warp per node) -------
__global__ void k_agg1g2(const float* __restrict__ b1, const float* __restrict__ W2) {
    __shared__ float sW[H1DIM * H2DIM];
    __shared__ float sb[H1DIM];
    for (int i = threadIdx.x; i < H1DIM * H2DIM; i += blockDim.x) sW[i] = tf32r(W2[i]);
    if (threadIdx.x < H1DIM) sb[threadIdx.x] = b1[threadIdx.x];
    __syncthreads();
    int warp = (blockIdx.x * blockDim.x + threadIdx.x) >> 5;
    int lane = threadIdx.x & 31;
    if (warp >= N_NODES) return;
    int d = warp;
    int start = g_rowptr[d], end = g_rowptr[d + 1];
    float dvd = g_dinv[d];
    float acc = g_h1s[d * H1DIM + lane];          // self loop (pre-scaled)
    for (int base = start; base < end; base += 32) {
        int n = end - base;
        int s = 0;
        if (lane < n) s = g_csrc[base + lane];
        int m = n < 32 ? n : 32;
#pragma unroll 8
        for (int j = 0; j < m; j++) {
            int sj = __shfl_sync(0xffffffffu, s, j);
            acc += g_h1s[sj * H1DIM + lane];
        }
    }
    float v = tf32r(fmaxf(acc * dvd + sb[lane], 0.0f));
    int j = lane & 15;
    float acc2 = 0.0f;
#pragma unroll
    for (int r = 0; r < 32; r++) {
        float xb = __shfl_sync(0xffffffffu, v, r);
        acc2 = fmaf(xb, sW[r * H2DIM + j], acc2);
    }
    if (lane < H2DIM) g_h2s[d * H2DIM + lane] = acc2 * dvd;   // pre-scale for layer 2
}

// ---- 8. FUSED agg2 + bias2 + relu + pool (TWO nodes per warp, half-warp) --
__global__ void k_agg2pool(const float* __restrict__ b2, const void* __restrict__ batch) {
    int warp = (blockIdx.x * blockDim.x + threadIdx.x) >> 5;
    int lane = threadIdx.x & 31;
    int is64 = g_bat64;
    int d = 2 * warp + (lane >> 4);        // node for this half-warp
    int l = lane & 15;                     // sub-lane within half
    if (d >= N_NODES) return;              // N_NODES even -> whole warp exits together
    int start = g_rowptr[d], end = g_rowptr[d + 1];
    int total = end - start;
    float dvd = g_dinv[d];
    float acc = g_h2s[d * H2DIM + l];      // self loop (pre-scaled)
    // uniform outer trip count across the warp keeps shfls convergent
    int iters = (total + 15) >> 4;
    int maxIters = __reduce_max_sync(0xffffffffu, iters);
    for (int t = 0; t < maxIters; t++) {
        int idx = start + t * 16 + l;
        int s = (idx < end) ? g_csrc[idx] : 0;
        int done = t * 16;
        int m = total - done; if (m > 16) m = 16; if (m < 0) m = 0;
#pragma unroll 8
        for (int j = 0; j < 16; j++) {
            int sj = __shfl_sync(0xffffffffu, s, j, 16);
            if (j < m) acc += g_h2s[sj * H2DIM + l];
        }
    }
    int g = clampi(load_idx(batch, d, is64), 0, N_GRAPHS - 1);
    float v = fmaxf(acc * dvd + b2[l], 0.0f);
    atomicAdd(&g_sum[g * H2DIM + l], v);
    if (l == 0) atomicAdd(&g_cnt[g], 1.0f);
}

// ---------------- 11. final: mean, FC (tf32), softmax ----------------------
__global__ void k_final(const float* __restrict__ fc_w, const float* __restrict__ fc_b,
                        float* __restrict__ out) {
    int g = blockIdx.x * blockDim.x + threadIdx.x;
    if (g >= N_GRAPHS) return;
    float inv = 1.0f / fmaxf(g_cnt[g], 1.0f);
    float p[H2DIM];
#pragma unroll
    for (int j = 0; j < H2DIM; j++) p[j] = tf32r(g_sum[g * H2DIM + j] * inv);
    float logit[NCLS];
#pragma unroll
    for (int c = 0; c < NCLS; c++) {
        float acc = 0.0f;
#pragma unroll
        for (int j = 0; j < H2DIM; j++) acc = fmaf(p[j], tf32r(fc_w[j * NCLS + c]), acc);
        logit[c] = acc + fc_b[c];
    }
    float m = logit[0];
#pragma unroll
    for (int c = 1; c < NCLS; c++) m = fmaxf(m, logit[c]);
    float s = 0.0f;
#pragma unroll
    for (int c = 0; c < NCLS; c++) { logit[c] = expf(logit[c] - m); s += logit[c]; }
    float invs = 1.0f / s;
#pragma unroll
    for (int c = 0; c < NCLS; c++) out[g * NCLS + c] = logit[c] * invs;
}

// ---------------------------------------------------------------------------
extern "C" void kernel_launch(void* const* d_in, const int* in_sizes, int n_in,
                              void* d_out, int out_size) {
    const float *x   = (n_in > 0) ? (const float*)d_in[0] : 0;
    const void  *ei  = (n_in > 1) ? d_in[1]               : 0;
    const void  *bat = (n_in > 2) ? d_in[2]               : 0;
    const float *W1  = (n_in > 3) ? (const float*)d_in[3] : 0;
    const float *b1  = (n_in > 4) ? (const float*)d_in[4] : 0;
    const float *W2  = (n_in > 5) ? (const float*)d_in[5] : 0;
    const float *b2  = (n_in > 6) ? (const float*)d_in[6] : 0;
    const float *fcw = (n_in > 7) ? (const float*)d_in[7] : 0;
    const float *fcb = (n_in > 8) ? (const float*)d_in[8] : 0;

    for (int i = 0; i < n_in; i++) {
        switch (in_sizes[i]) {
            case N_NODES * FEAT:   x   = (const float*)d_in[i]; break;
            case 2 * N_EDGES:      ei  = d_in[i];               break;
            case N_NODES:          bat = d_in[i];               break;
            case FEAT * H1DIM:     W1  = (const float*)d_in[i]; break;
            case H1DIM:            b1  = (const float*)d_in[i]; break;
            case H1DIM * H2DIM:    W2  = (const float*)d_in[i]; break;
            case H2DIM:            b2  = (const float*)d_in[i]; break;
            case H2DIM * NCLS:     fcw = (const float*)d_in[i]; break;
            case NCLS:             fcb = (const float*)d_in[i]; break;
            default: break;
        }
    }
    float* out = (float*)d_out;
    if (!x || !ei || !bat || !W1 || !b1 || !W2 || !b2 || !fcw || !fcb || !out) return;

    const int T = 256;
    k_probe   <<<1, 32>>>((const int*)ei, (const int*)bat);
    k_init    <<<(N_NODES + T - 1) / T, T>>>();
    k_deg     <<<(N_EDGES + T - 1) / T, T>>>(ei);
    k_bsum    <<<NBLK, SB>>>();
    k_bscan   <<<1, 128>>>();
    k_rowfill <<<NBLK, SB>>>();
    k_fill    <<<(N_EDGES + T - 1) / T, T>>>(ei);
    k_gemm1   <<<N_NODES / G1ROWS, 256>>>(x, W1);
    k_agg1g2  <<<(N_NODES * 32 + T - 1) / T, T>>>(b1, W2);
    k_agg2pool<<<(N_NODES / 2 * 32 + T - 1) / T, T>>>(b2, bat);
    k_final   <<<(N_GRAPHS + T - 1) / T, T>>>(fcw, fcb, out);
}